// round 6
// baseline (speedup 1.0000x reference)
#include <cuda_runtime.h>

// DihedralToCartesian R6: deeper segmentation (14 segments x 9 steps).
// CTA = 16 chains x 14 segments = 224 threads. Segment s>=1 starts from the
// canonical frame (entry geometry constant at boundaries i0 % 3 == 0), runs
// 9 steps locally; a 13-iteration per-chain compose (16 lanes) chains the
// rigid transforms; all 224 threads then transform records cooperatively and
// store straight to gmem (coalesced, stride-12B).

#define TPB    224
#define NRES   126
#define CHAINS 16
#define SEG    14
#define LSEG   9              // 9 % 3 == 0 -> canonical entry frame valid

__device__ __forceinline__ float frsqrt(float x) {
    float y;
    asm("rsqrt.approx.f32 %0, %1;" : "=f"(y) : "f"(x));
    return y;
}

__global__ void __launch_bounds__(TPB, 5)
dihedral_kernel(const float* __restrict__ angles,
                const float* __restrict__ prev,
                float* __restrict__ out)
{
    // buf: per (chain,step) 3-float record: sin/cos on load -> local points.
    __shared__ float buf[CHAINS * NRES * 3];      // 24192 B
    __shared__ float ex [CHAINS * SEG * 6];       // exit w, v (local coords)
    __shared__ float rp [CHAINS * SEG * 12];      // R columns g1,g2,g3 + p

    const int tid   = threadIdx.x;
    const int c     = tid / SEG;
    const int s     = tid - c * SEG;
    const int Bbase = blockIdx.x * CHAINS;

    float CA[3], SA[3], BOND[3];
    {
        const float alpha[3] = {2.028f, 2.124f, 1.941f};
        const float bond [3] = {1.329f, 1.458f, 1.523f};
        #pragma unroll
        for (int k = 0; k < 3; ++k) {
            CA[k] = cosf(alpha[k]);
            SA[k] = sinf(alpha[k]);
            BOND[k] = bond[k];
        }
    }

    // ---- phase 0: coalesced load of sin/cos into buf records ----
    const float* gang = angles + (size_t)Bbase * (2 * NRES);
    #pragma unroll
    for (int i = 0; i < (CHAINS * NRES) / TPB; ++i) {   // 9 iters
        int e  = tid + i * TPB;
        int cc = e / NRES;
        int j  = e - cc * NRES;
        buf[e * 3 + 0] = gang[cc * (2 * NRES) + j];          // sin
        buf[e * 3 + 1] = gang[cc * (2 * NRES) + NRES + j];   // cos
    }
    __syncthreads();

    // ---- phase 1: run LSEG steps locally ----
    float* rec = &buf[(c * NRES + s * LSEG) * 3];
    float px, py, pz, vx, vy, vz, wx, wy, wz;

    #define STEP(j, K) do {                                                     \
        float s_ = rec[(j) * 3 + 0], co = rec[(j) * 3 + 1];                     \
        float invn = frsqrt(fmaf(s_, s_, fmaf(co, co, 1e-8f)));                 \
        float t  = SA[K] * invn;                                                \
        float r1 =  t * co;                                                     \
        float r2 = -t * s_;                                                     \
        float cxx = wy * vz - wz * vy;                                          \
        float cxy = wz * vx - wx * vz;                                          \
        float cxz = wx * vy - wy * vx;                                          \
        float inr = frsqrt(fmaf(cxx, cxx, fmaf(cxy, cxy,                        \
                                fmaf(cxz, cxz, 1e-20f))));                      \
        float nx = cxx * inr, ny = cxy * inr, nz = cxz * inr;                   \
        float mx = wy * nz - wz * ny;                                           \
        float my = wz * nx - wx * nz;                                           \
        float mz = wx * ny - wy * nx;                                           \
        float ux = fmaf(-CA[K], wx, fmaf(r1, mx, r2 * nx));                     \
        float uy = fmaf(-CA[K], wy, fmaf(r1, my, r2 * ny));                     \
        float uz = fmaf(-CA[K], wz, fmaf(r1, mz, r2 * nz));                     \
        px = fmaf(BOND[K], ux, px);                                             \
        py = fmaf(BOND[K], uy, py);                                             \
        pz = fmaf(BOND[K], uz, pz);                                             \
        rec[(j) * 3 + 0] = px;                                                  \
        rec[(j) * 3 + 1] = py;                                                  \
        rec[(j) * 3 + 2] = pz;                                                  \
        float iun = frsqrt(fmaf(ux, ux, fmaf(uy, uy, uz * uz)));                \
        vx = wx; vy = wy; vz = wz;                                              \
        wx = ux * iun; wy = uy * iun; wz = uz * iun;                            \
    } while (0)

    if (s == 0) {
        // segment 0: real geometry from prev_three, reference-faithful step 0
        const float* pp = prev + (size_t)(Bbase + c) * 9;
        float ax = pp[0], ay = pp[1], az = pp[2];
        float bx = pp[3], by = pp[4], bz = pp[5];
        px = pp[6]; py = pp[7]; pz = pp[8];

        float s_ = rec[0], co = rec[1];
        float invn = frsqrt(fmaf(s_, s_, fmaf(co, co, 1e-8f)));
        float t = SA[0] * invn, r1 = t * co, r2 = -t * s_;

        float bcx = (bx - px) + 1e-8f;
        float bcy = (by - py) + 1e-8f;
        float bcz = (bz - pz) + 1e-8f;
        float ib = frsqrt(fmaf(bcx, bcx, fmaf(bcy, bcy, bcz * bcz)));
        bcx *= ib; bcy *= ib; bcz *= ib;

        float qx = bx - ax, qy = by - ay, qz = bz - az;
        float nx = fmaf(qy, bcz, fmaf(-qz, bcy, 1e-8f));
        float ny = fmaf(qz, bcx, fmaf(-qx, bcz, 1e-8f));
        float nz = fmaf(qx, bcy, fmaf(-qy, bcx, 1e-8f));
        float in_ = frsqrt(fmaf(nx, nx, fmaf(ny, ny, nz * nz)));
        nx *= in_; ny *= in_; nz *= in_;

        float mx = ny * bcz - nz * bcy;
        float my = nz * bcx - nx * bcz;
        float mz = nx * bcy - ny * bcx;

        float ux = fmaf(CA[0], bcx, fmaf(r1, mx, r2 * nx));
        float uy = fmaf(CA[0], bcy, fmaf(r1, my, r2 * ny));
        float uz = fmaf(CA[0], bcz, fmaf(r1, mz, r2 * nz));

        px = fmaf(BOND[0], ux, px);
        py = fmaf(BOND[0], uy, py);
        pz = fmaf(BOND[0], uz, pz);
        rec[0] = px; rec[1] = py; rec[2] = pz;

        float iun = frsqrt(fmaf(ux, ux, fmaf(uy, uy, uz * uz)));
        vx = -bcx; vy = -bcy; vz = -bcz;   // unit(c0 - b0)
        wx = ux * iun; wy = uy * iun; wz = uz * iun;
    } else {
        // canonical entry frame: w0 = e1, v0 = -CA[2]*e1 + SA[2]*e2, p = 0
        px = 0.f; py = 0.f; pz = 0.f;
        wx = 1.f; wy = 0.f; wz = 0.f;
        vx = -CA[2]; vy = SA[2]; vz = 0.f;
        STEP(0, 0);
    }
    STEP(1, 1); STEP(2, 2);
    STEP(3, 0); STEP(4, 1); STEP(5, 2);
    STEP(6, 0); STEP(7, 1); STEP(8, 2);
    #undef STEP

    {   // publish exit directions (exit point lives in rec[(LSEG-1)*3..])
        float* e6 = &ex[(c * SEG + s) * 6];
        e6[0] = wx; e6[1] = wy; e6[2] = wz;
        e6[3] = vx; e6[4] = vy; e6[5] = vz;
    }
    __syncthreads();

    // ---- phase 2: per-chain sequential compose (16 lanes) ----
    if (tid < CHAINS) {
        const int cc = tid;
        float* r0 = &rp[cc * SEG * 12];
        r0[0] = 1.f; r0[1] = 0.f; r0[2] = 0.f;
        r0[3] = 0.f; r0[4] = 1.f; r0[5] = 0.f;
        r0[6] = 0.f; r0[7] = 0.f; r0[8] = 1.f;
        r0[9] = 0.f; r0[10] = 0.f; r0[11] = 0.f;

        const float* e0 = &ex[cc * SEG * 6];
        const float* q0 = &buf[(cc * NRES + (LSEG - 1)) * 3];
        float pex = q0[0], pey = q0[1], pez = q0[2];
        float wex = e0[0], wey = e0[1], wez = e0[2];
        float vex = e0[3], vey = e0[4], vez = e0[5];

        #pragma unroll 1
        for (int ss = 1; ss < SEG; ++ss) {
            // Gram-Schmidt basis from entry (w, v)
            float d  = fmaf(vex, wex, fmaf(vey, wey, vez * wez));
            float tx = fmaf(-d, wex, vex);
            float ty = fmaf(-d, wey, vey);
            float tz = fmaf(-d, wez, vez);
            float it = frsqrt(fmaf(tx, tx, fmaf(ty, ty, fmaf(tz, tz, 1e-20f))));
            float g1x = wex,     g1y = wey,     g1z = wez;
            float g2x = tx * it, g2y = ty * it, g2z = tz * it;
            float g3x = g1y * g2z - g1z * g2y;
            float g3y = g1z * g2x - g1x * g2z;
            float g3z = g1x * g2y - g1y * g2x;

            float* rr = &rp[(cc * SEG + ss) * 12];
            rr[0] = g1x; rr[1] = g1y; rr[2] = g1z;
            rr[3] = g2x; rr[4] = g2y; rr[5] = g2z;
            rr[6] = g3x; rr[7] = g3y; rr[8] = g3z;
            rr[9] = pex; rr[10] = pey; rr[11] = pez;

            // chain exit -> next entry (in global coords)
            const float* es = &ex[(cc * SEG + ss) * 6];
            const float* qs = &buf[(cc * NRES + ss * LSEG + (LSEG - 1)) * 3];
            float qx = qs[0], qy = qs[1], qz = qs[2];
            float wfx = es[0], wfy = es[1], wfz = es[2];
            float vfx = es[3], vfy = es[4], vfz = es[5];

            float npx = pex + qx * g1x + qy * g2x + qz * g3x;
            float npy = pey + qx * g1y + qy * g2y + qz * g3y;
            float npz = pez + qx * g1z + qy * g2z + qz * g3z;
            wex = wfx * g1x + wfy * g2x + wfz * g3x;
            wey = wfx * g1y + wfy * g2y + wfz * g3y;
            wez = wfx * g1z + wfy * g2z + wfz * g3z;
            vex = vfx * g1x + vfy * g2x + vfz * g3x;
            vey = vfx * g1y + vfy * g2y + vfz * g3y;
            vez = vfx * g1z + vfy * g2z + vfz * g3z;
            pex = npx; pey = npy; pez = npz;
        }
    }
    __syncthreads();

    // ---- phase 3: cooperative transform + direct coalesced store ----
    float* gout = out + (size_t)Bbase * (NRES * 3);
    #pragma unroll
    for (int i = 0; i < (CHAINS * NRES) / TPB; ++i) {   // 9 iters
        int e  = tid + i * TPB;
        int cc = e / NRES;
        int j  = e - cc * NRES;
        int ss = j / LSEG;

        const float* rr = &rp[(cc * SEG + ss) * 12];
        float qx = buf[e * 3 + 0];
        float qy = buf[e * 3 + 1];
        float qz = buf[e * 3 + 2];
        gout[e * 3 + 0] = fmaf(qx, rr[0], fmaf(qy, rr[3], fmaf(qz, rr[6], rr[9])));
        gout[e * 3 + 1] = fmaf(qx, rr[1], fmaf(qy, rr[4], fmaf(qz, rr[7], rr[10])));
        gout[e * 3 + 2] = fmaf(qx, rr[2], fmaf(qy, rr[5], fmaf(qz, rr[8], rr[11])));
    }
}

extern "C" void kernel_launch(void* const* d_in, const int* in_sizes, int n_in,
                              void* d_out, int out_size)
{
    const float* angles = (const float*)d_in[0];   // (B, 252) f32
    const float* prev   = (const float*)d_in[1];   // (B, 3, 3) f32
    float*       out    = (float*)d_out;           // (B, 126, 3) f32

    const int B = in_sizes[0] / (2 * NRES);        // 65536
    dihedral_kernel<<<B / CHAINS, TPB>>>(angles, prev, out);
}